// round 17
// baseline (speedup 1.0000x reference)
#include <cuda_runtime.h>
#include <cuda_bf16.h>
#include <cstdint>

#define B_   4
#define C_   128
#define CQ_  16
#define N_   4096

__device__ __nv_bfloat16 g_q[B_ * N_ * CQ_];   // [B][N][16]  (q pre-scaled by log2e)
__device__ __nv_bfloat16 g_k[B_ * N_ * CQ_];   // [B][N][16]
__device__ uint8_t       g_v8[B_ * C_ * N_];   // [B][C][N]  e4m3, channel-major

extern __shared__ char dyn_smem[];

// ---------------------------------------------------------------------------
// Helpers
// ---------------------------------------------------------------------------
__device__ __forceinline__ uint32_t smem_to_u32(const void* p) {
    uint32_t a;
    asm("{ .reg .u64 t; cvta.to.shared.u64 t, %1; cvt.u32.u64 %0, t; }"
        : "=r"(a) : "l"(p));
    return a;
}
__device__ __forceinline__ void cp_async16(uint32_t dst, const void* src) {
    asm volatile("cp.async.cg.shared.global [%0], [%1], 16;"
                 :: "r"(dst), "l"(src) : "memory");
}
__device__ __forceinline__ void cp_commit() {
    asm volatile("cp.async.commit_group;" ::: "memory");
}
__device__ __forceinline__ void cp_wait0() {
    asm volatile("cp.async.wait_group 0;" ::: "memory");
}
__device__ __forceinline__ void cp_wait1() {
    asm volatile("cp.async.wait_group 1;" ::: "memory");
}
__device__ __forceinline__ void cp_wait2() {
    asm volatile("cp.async.wait_group 2;" ::: "memory");
}
__device__ __forceinline__ uint32_t lds32(uint32_t addr) {
    uint32_t v;
    asm volatile("ld.shared.b32 %0, [%1];" : "=r"(v) : "r"(addr));
    return v;
}
__device__ __forceinline__ void ldsm_x4(uint32_t* r, uint32_t addr) {
    asm volatile("ldmatrix.sync.aligned.m8n8.x4.shared.b16 {%0,%1,%2,%3}, [%4];"
                 : "=r"(r[0]), "=r"(r[1]), "=r"(r[2]), "=r"(r[3]) : "r"(addr));
}
__device__ __forceinline__ void ldsm_x4_trans(uint32_t* r, uint32_t addr) {
    asm volatile("ldmatrix.sync.aligned.m8n8.x4.trans.shared.b16 {%0,%1,%2,%3}, [%4];"
                 : "=r"(r[0]), "=r"(r[1]), "=r"(r[2]), "=r"(r[3]) : "r"(addr));
}
__device__ __forceinline__ void mma16816(float* d, const uint32_t* a,
                                         uint32_t b0, uint32_t b1) {
    asm volatile(
        "mma.sync.aligned.m16n8k16.row.col.f32.bf16.bf16.f32 "
        "{%0,%1,%2,%3}, {%4,%5,%6,%7}, {%8,%9}, {%0,%1,%2,%3};"
        : "+f"(d[0]), "+f"(d[1]), "+f"(d[2]), "+f"(d[3])
        : "r"(a[0]), "r"(a[1]), "r"(a[2]), "r"(a[3]), "r"(b0), "r"(b1));
}
// FP8 e4m3 MMA, m16n8k32, f32 accum (sm_89+)
__device__ __forceinline__ void mma_fp8(float* d, const uint32_t* a,
                                        uint32_t b0, uint32_t b1) {
    asm volatile(
        "mma.sync.aligned.m16n8k32.row.col.f32.e4m3.e4m3.f32 "
        "{%0,%1,%2,%3}, {%4,%5,%6,%7}, {%8,%9}, {%0,%1,%2,%3};"
        : "+f"(d[0]), "+f"(d[1]), "+f"(d[2]), "+f"(d[3])
        : "r"(a[0]), "r"(a[1]), "r"(a[2]), "r"(a[3]), "r"(b0), "r"(b1));
}
// pack two f32 -> f16x2, lo = first arg
__device__ __forceinline__ uint32_t cvt_f16x2(float lo, float hi) {
    uint32_t d;
    asm("cvt.rn.f16x2.f32 %0, %1, %2;" : "=r"(d) : "f"(hi), "f"(lo));
    return d;
}
__device__ __forceinline__ uint32_t ex2_f16x2(uint32_t x) {
    uint32_t d;
    asm("ex2.approx.f16x2 %0, %1;" : "=r"(d) : "r"(x));
    return d;
}
// f16x2 -> 2 e4m3 bytes (byte0 = lo half)
__device__ __forceinline__ uint32_t cvt_e4m3x2_f16x2(uint32_t x) {
    uint16_t d;
    asm("cvt.rn.satfinite.e4m3x2.f16x2 %0, %1;" : "=h"(d) : "r"(x));
    return (uint32_t)d;
}
// two f32 -> 2 e4m3 bytes (byte0 = lo)
__device__ __forceinline__ uint16_t e4m3x2_f32(float lo, float hi) {
    uint16_t d;
    asm("cvt.rn.satfinite.e4m3x2.f32 %0, %1, %2;" : "=h"(d) : "f"(hi), "f"(lo));
    return d;
}
__device__ __forceinline__ uint32_t prmt(uint32_t a, uint32_t b, uint32_t sel) {
    uint32_t d;
    asm("prmt.b32 %0, %1, %2, %3;" : "=r"(d) : "r"(a), "r"(b), "r"(sel));
    return d;
}
// pack: low half = a, high half = b
#define CVT_BF16X2_F32(result, a, b) \
    asm("cvt.rn.satfinite.bf16x2.f32 %0, %1, %2;" : "=r"(result) : "f"(b), "f"(a))

#define ONES_E4M3X4 0x38383838u

// ---------------------------------------------------------------------------
// Projection on tensor cores (q pre-scaled by log2e); V written as e4m3
// ---------------------------------------------------------------------------
#define PJ_WS   0
#define PJ_XS   43520
#define PJ_BS   78336
#define PROJ_SM_BYTES (PJ_BS + 640)
#define LOG2E_F 1.44269504088896f

__global__ __launch_bounds__(256, 1)
void proj_kernel(const float* __restrict__ x,
                 const float* __restrict__ wq, const float* __restrict__ bq,
                 const float* __restrict__ wk, const float* __restrict__ bk,
                 const float* __restrict__ wv, const float* __restrict__ bv) {
    char* sm = dyn_smem;
    const uint32_t smb = smem_to_u32(sm);
    __nv_bfloat16* Ws = (__nv_bfloat16*)(sm + PJ_WS);
    __nv_bfloat16* Xs = (__nv_bfloat16*)(sm + PJ_XS);
    float* Bs = (float*)(sm + PJ_BS);

    const int tid = threadIdx.x;
    const int b   = blockIdx.y;
    const int n0  = blockIdx.x * 128;

    for (int idx = tid; idx < 160 * 32; idx += 256) {
        int ch = idx >> 5, cq = (idx & 31) * 4;
        const float* wsrc = (ch < 16) ? (wq + ch * 128 + cq)
                          : (ch < 32) ? (wk + (ch - 16) * 128 + cq)
                                      : (wv + (ch - 32) * 128 + cq);
        float4 wv4 = *(const float4*)wsrc;
        if (ch < 16) {
            wv4.x *= LOG2E_F; wv4.y *= LOG2E_F;
            wv4.z *= LOG2E_F; wv4.w *= LOG2E_F;
        }
        uint32_t p0, p1;
        CVT_BF16X2_F32(p0, wv4.x, wv4.y);
        CVT_BF16X2_F32(p1, wv4.z, wv4.w);
        *(uint2*)(Ws + ch * 136 + cq) = make_uint2(p0, p1);
    }
    if (tid < 160)
        Bs[tid] = (tid < 16) ? (bq[tid] * LOG2E_F)
                : (tid < 32) ? bk[tid - 16] : bv[tid - 32];

    const float* xb = x + (size_t)b * C_ * N_ + n0;
    for (int idx = tid; idx < 128 * 32; idx += 256) {
        int c = idx >> 5, jq = (idx & 31) * 4;
        float4 xv = *(const float4*)(xb + (size_t)c * N_ + jq);
        uint32_t p0, p1;
        CVT_BF16X2_F32(p0, xv.x, xv.y);
        CVT_BF16X2_F32(p1, xv.z, xv.w);
        *(uint2*)(Xs + c * 136 + jq) = make_uint2(p0, p1);
    }
    __syncthreads();

    const int w  = tid >> 5;
    const int l  = tid & 31;
    const int gr = l >> 2, qd = l & 3;
    const int grp = l >> 3, lr = l & 7;
    const int nw = 16 * w;

    float acc[10][2][4];
    #pragma unroll
    for (int mf = 0; mf < 10; mf++)
        #pragma unroll
        for (int nf = 0; nf < 2; nf++)
            #pragma unroll
            for (int i = 0; i < 4; i++) acc[mf][nf][i] = 0.f;

    const uint32_t xbase = smb + PJ_XS
        + (uint32_t)((grp & 1) * 8 + lr) * 272u + (uint32_t)(nw + (grp >> 1) * 8) * 2u;
    const uint32_t wbase = smb + PJ_WS
        + (uint32_t)((grp & 1) * 8 + lr) * 272u + (uint32_t)((grp >> 1) * 8) * 2u;

    #pragma unroll
    for (int kk = 0; kk < 8; kk++) {
        uint32_t bx[4];
        ldsm_x4_trans(bx, xbase + kk * 16 * 272u);
        #pragma unroll
        for (int mf = 0; mf < 10; mf++) {
            uint32_t aw[4];
            ldsm_x4(aw, wbase + (uint32_t)(mf * 16) * 272u + kk * 32u);
            mma16816(acc[mf][0], aw, bx[0], bx[1]);
            mma16816(acc[mf][1], aw, bx[2], bx[3]);
        }
    }

    #pragma unroll
    for (int mf = 0; mf < 10; mf++) {
        int ch0 = 16 * mf + gr;
        float b0 = Bs[ch0], b1 = Bs[ch0 + 8];
        #pragma unroll
        for (int nf = 0; nf < 2; nf++) {
            int pos = n0 + nw + 8 * nf + 2 * qd;
            float v00 = acc[mf][nf][0] + b0, v01 = acc[mf][nf][1] + b0;
            float v10 = acc[mf][nf][2] + b1, v11 = acc[mf][nf][3] + b1;
            if (mf == 0) {
                g_q[(size_t)(b * N_ + pos) * 16 + ch0]         = __float2bfloat16(v00);
                g_q[(size_t)(b * N_ + pos + 1) * 16 + ch0]     = __float2bfloat16(v01);
                g_q[(size_t)(b * N_ + pos) * 16 + ch0 + 8]     = __float2bfloat16(v10);
                g_q[(size_t)(b * N_ + pos + 1) * 16 + ch0 + 8] = __float2bfloat16(v11);
            } else if (mf == 1) {
                int c = ch0 - 16;
                g_k[(size_t)(b * N_ + pos) * 16 + c]         = __float2bfloat16(v00);
                g_k[(size_t)(b * N_ + pos + 1) * 16 + c]     = __float2bfloat16(v01);
                g_k[(size_t)(b * N_ + pos) * 16 + c + 8]     = __float2bfloat16(v10);
                g_k[(size_t)(b * N_ + pos + 1) * 16 + c + 8] = __float2bfloat16(v11);
            } else {
                int c = ch0 - 32;
                *(uint16_t*)(g_v8 + (size_t)(b * C_ + c) * N_ + pos)     = e4m3x2_f32(v00, v01);
                *(uint16_t*)(g_v8 + (size_t)(b * C_ + c + 8) * N_ + pos) = e4m3x2_f32(v10, v11);
            }
        }
    }
}

// ---------------------------------------------------------------------------
// Flash attention R17: R16 skeleton, MMA2 + rowsums on FP8 (m16n8k32 e4m3).
// 512 threads, 16 warps = 8 row-groups x 2 j-halves; warp: 16 rows x 64 j x
// 128 ch. V tiles e4m3 (pitch 144). P built via f16x2 ex2 -> e4m3x2 -> quad
// SHFL/PRMT repack into k32 A-fragments.
// smem: Vs 4x18432 | Ks 4x4096 @73728 | Qs @90112 | Ls @94208.
// ---------------------------------------------------------------------------
#define VS_OFF 0
#define VS_BUF 18432                   /* 128 ch x 144 B */
#define KS_OFF (4 * VS_BUF)            /* 73728 */
#define KS_BUF 4096
#define QS_OFF (KS_OFF + 4 * KS_BUF)   /* 90112 */
#define LS_OFF (QS_OFF + 4096)         /* 94208 */
#define ATTN_SM_BYTES (LS_OFF + 512)

__global__ __launch_bounds__(512, 1)
void attn_kernel(const float* __restrict__ x, const float* __restrict__ gamma,
                 float* __restrict__ out) {
    char* sm = dyn_smem;
    const uint32_t smb = smem_to_u32(sm);

    const int tid = threadIdx.x;
    const int w   = tid >> 5;
    const int l   = tid & 31;
    const int gr  = l >> 2;
    const int qd  = l & 3;
    const int grp = l >> 3;
    const int lr  = l & 7;
    const int rg  = w >> 1;        // row group: rows 16*rg .. +15
    const int jh  = w & 1;         // j half of each tile
    const int b   = blockIdx.y;
    const int i0  = blockIdx.x * 128;

    // ---- prologue: Q + tiles 0 and 1 (two commit groups) ----
    if (tid < 256) {
        int row = tid >> 1, half = tid & 1;
        cp_async16(smb + QS_OFF + row * 32 + half * 16,
                   (const char*)g_q + ((size_t)(b * N_ + i0 + row) * 16 + half * 8) * 2);
    }
    #pragma unroll
    for (int pt = 0; pt < 2; pt++) {
        const int j0 = pt * 128;
        if (tid < 256) {
            int row = tid >> 1, half = tid & 1;
            cp_async16(smb + KS_OFF + pt * KS_BUF + row * 32 + half * 16,
                       (const char*)g_k + ((size_t)(b * N_ + j0 + row) * 16 + half * 8) * 2);
        }
        #pragma unroll
        for (int u = 0; u < 2; u++) {
            int idx = tid + 512 * u;
            int r = idx >> 3, col = idx & 7;
            cp_async16(smb + VS_OFF + pt * VS_BUF + r * 144 + col * 16,
                       g_v8 + (size_t)(b * C_ + r) * N_ + j0 + col * 16);
        }
        cp_commit();
    }
    __syncthreads();

    cp_wait1();        // group 0 (Q + tile 0) complete
    __syncthreads();
    uint32_t qa[4];
    {
        uint32_t qb = smb + QS_OFF + (16 * rg + gr) * 32 + qd * 4;
        qa[0] = lds32(qb);
        qa[1] = lds32(qb + 8 * 32);
        qa[2] = lds32(qb + 16);
        qa[3] = lds32(qb + 8 * 32 + 16);
    }

    const uint32_t klane = (8 * (grp >> 1) + lr) * 32 + 16 * (grp & 1);
    const uint32_t vlane = (8 * (grp >> 1) + lr) * 144 + 16 * (grp & 1);
    const int src0 = (l & ~3) | (2 * (qd & 1));
    const uint32_t psel = (qd >> 1) ? 0x7632u : 0x5410u;

    float O[16][4];
    #pragma unroll
    for (int nt = 0; nt < 16; nt++)
        #pragma unroll
        for (int i = 0; i < 4; i++) O[nt][i] = 0.f;
    float ls[4] = {0.f, 0.f, 0.f, 0.f};

    #pragma unroll 1
    for (int t = 0; t < 32; t++) {
        if (t >= 2 && (t & 1) == 0) __syncthreads();

        if (t + 2 < 32) {
            const int j1 = (t + 2) * 128;
            const int nb = (t + 2) & 3;
            if (tid < 256) {
                int row = tid >> 1, half = tid & 1;
                cp_async16(smb + KS_OFF + nb * KS_BUF + row * 32 + half * 16,
                           (const char*)g_k + ((size_t)(b * N_ + j1 + row) * 16 + half * 8) * 2);
            }
            #pragma unroll
            for (int u = 0; u < 2; u++) {
                int idx = tid + 512 * u;
                int r = idx >> 3, col = idx & 7;
                cp_async16(smb + VS_OFF + nb * VS_BUF + r * 144 + col * 16,
                           g_v8 + (size_t)(b * C_ + r) * N_ + j1 + col * 16);
            }
            cp_commit();
        }

        if (t + 2 < 32) cp_wait2();
        else if (t + 1 < 32) cp_wait1();
        else cp_wait0();

        const uint32_t kb = smb + KS_OFF + (uint32_t)(t & 3) * KS_BUF
                          + (uint32_t)jh * 2048u;
        const uint32_t vb = smb + VS_OFF + (uint32_t)(t & 3) * VS_BUF
                          + (uint32_t)jh * 64u;

        #pragma unroll
        for (int kk = 0; kk < 2; kk++) {       // two k32 steps over the 64-j half
            uint32_t w02[2], w13[2];
            #pragma unroll
            for (int cc = 0; cc < 2; cc++) {   // two k16 sub-steps
                const int c = 2 * kk + cc;
                uint32_t kr[4];
                ldsm_x4(kr, kb + klane + c * 512);
                float sa0[4] = {0.f, 0.f, 0.f, 0.f};
                float sa1[4] = {0.f, 0.f, 0.f, 0.f};
                mma16816(sa0, qa, kr[0], kr[1]);
                mma16816(sa1, qa, kr[2], kr[3]);
                uint32_t h0 = ex2_f16x2(cvt_f16x2(sa0[0], sa0[1]));
                uint32_t h1 = ex2_f16x2(cvt_f16x2(sa0[2], sa0[3]));
                uint32_t h2 = ex2_f16x2(cvt_f16x2(sa1[0], sa1[1]));
                uint32_t h3 = ex2_f16x2(cvt_f16x2(sa1[2], sa1[3]));
                uint32_t b0 = cvt_e4m3x2_f16x2(h0);   // row gr,   j 2qd pair
                uint32_t b1 = cvt_e4m3x2_f16x2(h1);   // row gr+8, j 2qd pair
                uint32_t b2 = cvt_e4m3x2_f16x2(h2);   // row gr,   j 8+2qd pair
                uint32_t b3 = cvt_e4m3x2_f16x2(h3);   // row gr+8
                w02[cc] = b0 | (b2 << 16);
                w13[cc] = b1 | (b3 << 16);
            }
            // quad repack -> fp8 A fragment (k = 32 j of this step)
            uint32_t Af[4];
            {
                uint32_t u0 = __shfl_sync(0xffffffffu, w02[0], src0);
                uint32_t u1 = __shfl_sync(0xffffffffu, w02[0], src0 + 1);
                Af[0] = prmt(u0, u1, psel);
                u0 = __shfl_sync(0xffffffffu, w13[0], src0);
                u1 = __shfl_sync(0xffffffffu, w13[0], src0 + 1);
                Af[1] = prmt(u0, u1, psel);
                u0 = __shfl_sync(0xffffffffu, w02[1], src0);
                u1 = __shfl_sync(0xffffffffu, w02[1], src0 + 1);
                Af[2] = prmt(u0, u1, psel);
                u0 = __shfl_sync(0xffffffffu, w13[1], src0);
                u1 = __shfl_sync(0xffffffffu, w13[1], src0 + 1);
                Af[3] = prmt(u0, u1, psel);
            }

            // rowsums on the tensor core (fp8 ones)
            mma_fp8(ls, Af, ONES_E4M3X4, ONES_E4M3X4);

            // MMA2 fp8: 8 ntp blocks of 16 channels
            #pragma unroll
            for (int ntp = 0; ntp < 8; ntp++) {
                uint32_t vr[4];
                ldsm_x4(vr, vb + vlane + (uint32_t)ntp * 2304u + (uint32_t)kk * 32u);
                mma_fp8(O[2 * ntp],     Af, vr[0], vr[1]);
                mma_fp8(O[2 * ntp + 1], Af, vr[2], vr[3]);
            }
        }
    }

    // ---- epilogue: merge jh halves, normalize, residual ----
    __syncthreads();

    float* Osm = (float*)sm;                 // [128][129] over Vs region
    float* Ls1 = (float*)(sm + LS_OFF);      // jh=1 partial rowsums [128]
    const int r0 = 16 * rg + gr, r1 = r0 + 8;

    if (jh == 1) {
        if (qd == 0) { Ls1[r0] = ls[0]; Ls1[r1] = ls[2]; }
        #pragma unroll
        for (int nt = 0; nt < 16; nt++) {
            int c = 8 * nt + 2 * qd;
            Osm[r0 * 129 + c]     = O[nt][0];
            Osm[r0 * 129 + c + 1] = O[nt][1];
            Osm[r1 * 129 + c]     = O[nt][2];
            Osm[r1 * 129 + c + 1] = O[nt][3];
        }
    }
    __syncthreads();
    if (jh == 0) {
        const float inv0 = 1.0f / (ls[0] + Ls1[r0]);
        const float inv1 = 1.0f / (ls[2] + Ls1[r1]);
        #pragma unroll
        for (int nt = 0; nt < 16; nt++) {
            int c = 8 * nt + 2 * qd;
            Osm[r0 * 129 + c]     = (Osm[r0 * 129 + c]     + O[nt][0]) * inv0;
            Osm[r0 * 129 + c + 1] = (Osm[r0 * 129 + c + 1] + O[nt][1]) * inv0;
            Osm[r1 * 129 + c]     = (Osm[r1 * 129 + c]     + O[nt][2]) * inv1;
            Osm[r1 * 129 + c + 1] = (Osm[r1 * 129 + c + 1] + O[nt][3]) * inv1;
        }
    }
    __syncthreads();

    const float gm = gamma[0];
    #pragma unroll 4
    for (int it = 0; it < 32; it++) {
        int idx = tid + 512 * it;
        int c = idx >> 7, il = idx & 127;
        size_t gi = (size_t)(b * C_ + c) * N_ + i0 + il;
        out[gi] = gm * Osm[il * 129 + c] + x[gi];
    }
}

// ---------------------------------------------------------------------------
extern "C" void kernel_launch(void* const* d_in, const int* in_sizes, int n_in,
                              void* d_out, int out_size) {
    (void)in_sizes; (void)n_in; (void)out_size;
    const float* x     = (const float*)d_in[0];
    const float* wq    = (const float*)d_in[1];
    const float* bq    = (const float*)d_in[2];
    const float* wk    = (const float*)d_in[3];
    const float* bk    = (const float*)d_in[4];
    const float* wv    = (const float*)d_in[5];
    const float* bv    = (const float*)d_in[6];
    const float* gamma = (const float*)d_in[7];
    float* out = (float*)d_out;

    cudaFuncSetAttribute(proj_kernel, cudaFuncAttributeMaxDynamicSharedMemorySize,
                         PROJ_SM_BYTES);
    cudaFuncSetAttribute(attn_kernel, cudaFuncAttributeMaxDynamicSharedMemorySize,
                         ATTN_SM_BYTES);

    proj_kernel<<<dim3(32, 4), 256, PROJ_SM_BYTES>>>(x, wq, bq, wk, bk, wv, bv);
    attn_kernel<<<dim3(32, 4), 512, ATTN_SM_BYTES>>>(x, gamma, out);
}